// round 5
// baseline (speedup 1.0000x reference)
#include <cuda_runtime.h>
#include <math_constants.h>
#include <stdint.h>

#define N_BINS    15
#define C_DIM     100
#define TILE_ROWS 112
#define THREADS   256

__device__ float  g_cnt[N_BINS];
__device__ double g_conf[N_BINS];
__device__ float  g_accs[N_BINS];
__device__ int    g_is64;   // 1 if labels are int64, 0 if int32

// Zero accumulators AND detect label dtype (odd int32 words all zero => int64).
__global__ void ece_zero_kernel(const int* __restrict__ labels32, int n) {
    __shared__ int s_any;
    if (threadIdx.x == 0) s_any = 0;
    __syncthreads();

    if (threadIdx.x < N_BINS) {
        g_cnt[threadIdx.x]  = 0.0f;
        g_conf[threadIdx.x] = 0.0;
        g_accs[threadIdx.x] = 0.0f;
    }

    int any = 0;
    for (int idx = 1 + 2 * threadIdx.x; idx < n; idx += 2 * blockDim.x) {
        if (labels32[idx] != 0) { any = 1; break; }
    }
    if (any) atomicOr(&s_any, 1);
    __syncthreads();
    if (threadIdx.x == 0) g_is64 = (s_any == 0) ? 1 : 0;
}

__global__ void __launch_bounds__(THREADS) ece_accum_kernel(
    const float* __restrict__ logits,
    const void*  __restrict__ labels_raw,
    int n, int vec_ok)
{
    __shared__ float  tile[TILE_ROWS * C_DIM];   // 44.8 KB
    __shared__ float  s_cnt[N_BINS];
    __shared__ double s_conf[N_BINS];
    __shared__ float  s_acc[N_BINS];

    const int tid = threadIdx.x;
    if (tid < N_BINS) {
        s_cnt[tid]  = 0.0f;
        s_conf[tid] = 0.0;
        s_acc[tid]  = 0.0f;
    }

    const int base = blockIdx.x * TILE_ROWS;
    const int rows = min(TILE_ROWS, n - base);

    // ---- Phase 1: coalesced streaming copy global -> shared ----
    if (vec_ok) {
        const float4* __restrict__ src =
            reinterpret_cast<const float4*>(logits) + (size_t)base * 25;
        float4* dst = reinterpret_cast<float4*>(tile);
        const int nvec = rows * 25;
        #pragma unroll 4
        for (int i = tid; i < nvec; i += THREADS) dst[i] = src[i];
    } else {
        const float* __restrict__ src = logits + (size_t)base * C_DIM;
        const int nflt = rows * C_DIM;
        for (int i = tid; i < nflt; i += THREADS) tile[i] = src[i];
    }
    __syncthreads();

    // ---- Phase 2: thread-per-row max/argmax from shared ----
    if (tid < rows) {
        const float4* rp = reinterpret_cast<const float4*>(tile + tid * C_DIM);

        // 4 independent chains (one per float4 component) for ILP.
        float4 v0 = rp[0];
        float m0 = v0.x, m1 = v0.y, m2 = v0.z, m3 = v0.w;
        int   i0 = 0,    i1 = 0,    i2 = 0,    i3 = 0;
        #pragma unroll
        for (int i = 1; i < 25; i++) {
            float4 v = rp[i];
            if (v.x > m0) { m0 = v.x; i0 = i; }
            if (v.y > m1) { m1 = v.y; i1 = i; }
            if (v.z > m2) { m2 = v.z; i2 = i; }
            if (v.w > m3) { m3 = v.w; i3 = i; }
        }
        // Merge with explicit index tie-break (first occurrence wins,
        // matching jnp.argmax even on exact value collisions).
        float m  = m0; int mi = 4 * i0;
        { int c = 4 * i1 + 1; if (m1 > m || (m1 == m && c < mi)) { m = m1; mi = c; } }
        { int c = 4 * i2 + 2; if (m2 > m || (m2 == m && c < mi)) { m = m2; mi = c; } }
        { int c = 4 * i3 + 3; if (m3 > m || (m3 == m && c < mi)) { m = m3; mi = c; } }

        // sigmoid monotone: conf = sigmoid(max logit); argmax unchanged
        float conf = 1.0f / (1.0f + __expf(-m));
        // searchsorted(linspace(0,1,16), conf, 'left') - 1, clipped.
        // conf in (0,1): bin = ceil(conf*15) - 1.
        int bin = (int)ceilf(conf * 15.0f) - 1;
        bin = bin < 0 ? 0 : (bin > N_BINS - 1 ? N_BINS - 1 : bin);

        int lab;
        if (g_is64) lab = (int)((const long long*)labels_raw)[base + tid];
        else        lab = ((const int*)labels_raw)[base + tid];

        atomicAdd(&s_cnt[bin], 1.0f);
        atomicAdd(&s_conf[bin], (double)conf);
        atomicAdd(&s_acc[bin], (mi == lab) ? 1.0f : 0.0f);
    }
    __syncthreads();

    // ---- Flush block-local histogram ----
    if (tid < N_BINS) {
        float c = s_cnt[tid];
        if (c != 0.0f) {
            atomicAdd(&g_cnt[tid],  c);
            atomicAdd(&g_conf[tid], s_conf[tid]);
            atomicAdd(&g_accs[tid], s_acc[tid]);
        }
    }
}

__global__ void ece_final_kernel(float* __restrict__ out, float inv_n) {
    if (threadIdx.x == 0 && blockIdx.x == 0) {
        float ece = 0.0f;
        #pragma unroll
        for (int b = 0; b < N_BINS; b++) {
            float cnt = g_cnt[b];
            if (cnt > 0.0f) {
                float avg_conf = (float)g_conf[b] / cnt;
                float avg_acc  = g_accs[b] / cnt;
                ece += (avg_conf - avg_acc) * (cnt * inv_n);
            }
        }
        out[0] = ece;
    }
}

extern "C" void kernel_launch(void* const* d_in, const int* in_sizes, int n_in,
                              void* d_out, int out_size) {
    // Resolve input order by element count (logits = C_DIM x labels count).
    long long s0 = in_sizes[0], s1 = in_sizes[1];
    int logits_idx = (s0 > s1) ? 0 : 1;
    int labels_idx = 1 - logits_idx;

    const float* logits     = (const float*)d_in[logits_idx];
    const void*  labels_raw = d_in[labels_idx];
    int n = (int)((s0 < s1) ? s0 : s1);
    float* out = (float*)d_out;

    int vec_ok = ((uintptr_t)logits & 15) == 0 ? 1 : 0;

    ece_zero_kernel<<<1, 256>>>((const int*)labels_raw, n);

    int blocks = (n + TILE_ROWS - 1) / TILE_ROWS;
    ece_accum_kernel<<<blocks, THREADS>>>(logits, labels_raw, n, vec_ok);

    ece_final_kernel<<<1, 32>>>(out, 1.0f / (float)n);
}

// round 6
// speedup vs baseline: 2.6053x; 2.6053x over previous
#include <cuda_runtime.h>
#include <math_constants.h>
#include <stdint.h>

#define N_BINS  15
#define C_DIM   100
#define FULL    0xffffffffu
#define THREADS 256
#define BLOCKS  2368

__device__ float  g_cnt[N_BINS];
__device__ double g_conf[N_BINS];
__device__ float  g_accs[N_BINS];
__device__ int    g_is64;   // 1 if labels are int64, 0 if int32

// Zero accumulators AND detect label dtype (odd int32 words all zero => int64).
__global__ void ece_zero_kernel(const int* __restrict__ labels32, int n) {
    __shared__ int s_any;
    if (threadIdx.x == 0) s_any = 0;
    __syncthreads();

    if (threadIdx.x < N_BINS) {
        g_cnt[threadIdx.x]  = 0.0f;
        g_conf[threadIdx.x] = 0.0;
        g_accs[threadIdx.x] = 0.0f;
    }

    int limit = min(n, 8192);          // enough evidence; keep this kernel tiny
    int any = 0;
    for (int idx = 1 + 2 * threadIdx.x; idx < limit; idx += 2 * blockDim.x) {
        if (labels32[idx] != 0) { any = 1; break; }
    }
    if (any) atomicOr(&s_any, 1);
    __syncthreads();
    if (threadIdx.x == 0) g_is64 = (s_any == 0) ? 1 : 0;
}

// Order-preserving float -> u32 map (u32 compare == float compare)
__device__ __forceinline__ unsigned fmap(float f) {
    unsigned b = __float_as_uint(f);
    return ((int)b >= 0) ? (b | 0x80000000u) : ~b;
}

__global__ void __launch_bounds__(THREADS) ece_accum_kernel(
    const float* __restrict__ logits,
    const void*  __restrict__ labels_raw,
    int n, int vec_ok)
{
    const int is64 = g_is64;
    const int* __restrict__       lab32 = (const int*)labels_raw;
    const long long* __restrict__ lab64 = (const long long*)labels_raw;

    const int lane   = threadIdx.x & 31;
    const int warp   = (int)((blockIdx.x * blockDim.x + threadIdx.x) >> 5);
    const int nwarps = (BLOCKS * THREADS) >> 5;

    // Per-warp register histogram: lane b (b < 15) owns bin b.
    float r_cnt = 0.0f, r_conf = 0.0f, r_acc = 0.0f;

    for (int row = warp; row < n; row += nwarps) {
        float m  = -CUDART_INF_F;
        int   mi = 0x7fffffff;

        if (vec_ok) {
            if (lane < 25) {
                float4 v = reinterpret_cast<const float4*>(logits)
                               [(size_t)row * 25 + lane];
                int base = lane * 4;
                m = v.x; mi = base;                      // strict > keeps
                if (v.y > m) { m = v.y; mi = base + 1; } // first index
                if (v.z > m) { m = v.z; mi = base + 2; }
                if (v.w > m) { m = v.w; mi = base + 3; }
            }
        } else {
            #pragma unroll
            for (int j = 0; j < 4; j++) {
                int c = lane + j * 32;
                if (c < C_DIM) {
                    float x = logits[(size_t)row * C_DIM + c];
                    if (x > m) { m = x; mi = c; }
                }
            }
        }

        // Labels: all lanes load the same address -> 1 broadcast transaction.
        int lab = is64 ? (int)lab64[row] : lab32[row];

        // Warp argmax: redux over mapped value; ballot+ffs selects the
        // lowest winning lane == lowest column group (jnp first-index).
        unsigned mu   = fmap(m);
        unsigned maxu = __reduce_max_sync(FULL, mu);
        unsigned wm   = __ballot_sync(FULL, mu == maxu);
        int src = __ffs(wm) - 1;
        float mm  = __shfl_sync(FULL, m,  src);
        int   ami = __shfl_sync(FULL, mi, src);

        // Computed redundantly on all lanes (1 warp-instruction each).
        float conf = 1.0f / (1.0f + __expf(-mm));
        // searchsorted(linspace(0,1,16), conf, 'left') - 1, clipped;
        // conf in (0,1) -> bin = ceil(conf*15) - 1.
        int bin = (int)ceilf(conf * 15.0f) - 1;
        bin = bin < 0 ? 0 : (bin > N_BINS - 1 ? N_BINS - 1 : bin);

        if (lane == bin) {                 // lane-owned bin accumulation
            r_cnt  += 1.0f;
            r_conf += conf;
            r_acc  += (ami == lab) ? 1.0f : 0.0f;
        }
    }

    // Flush: 3 global atomics per lane (<15) per warp for the whole kernel.
    if (lane < N_BINS && r_cnt != 0.0f) {
        atomicAdd(&g_cnt[lane],  r_cnt);
        atomicAdd(&g_conf[lane], (double)r_conf);
        atomicAdd(&g_accs[lane], r_acc);
    }
}

__global__ void ece_final_kernel(float* __restrict__ out, float inv_n) {
    if (threadIdx.x == 0 && blockIdx.x == 0) {
        float ece = 0.0f;
        #pragma unroll
        for (int b = 0; b < N_BINS; b++) {
            float cnt = g_cnt[b];
            if (cnt > 0.0f) {
                float avg_conf = (float)g_conf[b] / cnt;
                float avg_acc  = g_accs[b] / cnt;
                ece += (avg_conf - avg_acc) * (cnt * inv_n);
            }
        }
        out[0] = ece;
    }
}

extern "C" void kernel_launch(void* const* d_in, const int* in_sizes, int n_in,
                              void* d_out, int out_size) {
    // Resolve input order by element count (logits = C_DIM x labels count).
    long long s0 = in_sizes[0], s1 = in_sizes[1];
    int logits_idx = (s0 > s1) ? 0 : 1;
    int labels_idx = 1 - logits_idx;

    const float* logits     = (const float*)d_in[logits_idx];
    const void*  labels_raw = d_in[labels_idx];
    int n = (int)((s0 < s1) ? s0 : s1);
    float* out = (float*)d_out;

    int vec_ok = ((uintptr_t)logits & 15) == 0 ? 1 : 0;

    ece_zero_kernel<<<1, 256>>>((const int*)labels_raw, n);
    ece_accum_kernel<<<BLOCKS, THREADS>>>(logits, labels_raw, n, vec_ok);
    ece_final_kernel<<<1, 32>>>(out, 1.0f / (float)n);
}

// round 7
// speedup vs baseline: 3.2968x; 1.2654x over previous
#include <cuda_runtime.h>
#include <math_constants.h>
#include <stdint.h>

#define N_BINS  15
#define C_DIM   100
#define FULL    0xffffffffu
#define THREADS 256
#define BLOCKS  2368

__device__ float  g_cnt[N_BINS];
__device__ double g_conf[N_BINS];
__device__ float  g_accs[N_BINS];
__device__ int    g_is64;   // 1 if labels are int64, 0 if int32

// Zero accumulators AND detect label dtype (odd int32 words all zero => int64).
__global__ void ece_zero_kernel(const int* __restrict__ labels32, int n) {
    __shared__ int s_any;
    if (threadIdx.x == 0) s_any = 0;
    __syncthreads();

    if (threadIdx.x < N_BINS) {
        g_cnt[threadIdx.x]  = 0.0f;
        g_conf[threadIdx.x] = 0.0;
        g_accs[threadIdx.x] = 0.0f;
    }

    int limit = min(n, 1024);   // plenty of evidence (P[false-int64] ~ 0)
    int any = 0;
    for (int idx = 1 + 2 * threadIdx.x; idx < limit; idx += 2 * blockDim.x) {
        if (labels32[idx] != 0) { any = 1; break; }
    }
    if (any) atomicOr(&s_any, 1);
    __syncthreads();
    if (threadIdx.x == 0) g_is64 = (s_any == 0) ? 1 : 0;
}

// Order-preserving float -> u32 map (u32 compare == float compare)
__device__ __forceinline__ unsigned fmap(float f) {
    unsigned b = __float_as_uint(f);
    return ((int)b >= 0) ? (b | 0x80000000u) : ~b;
}

__global__ void __launch_bounds__(THREADS) ece_accum_kernel(
    const float* __restrict__ logits,
    const void*  __restrict__ labels_raw,
    int n, int vec_ok)
{
    const int is64 = g_is64;
    const int* __restrict__       lab32 = (const int*)labels_raw;
    const long long* __restrict__ lab64 = (const long long*)labels_raw;

    const int lane   = threadIdx.x & 31;
    const int warp   = (int)((blockIdx.x * blockDim.x + threadIdx.x) >> 5);
    const int nwarps = (BLOCKS * THREADS) >> 5;

    // Per-warp register histogram: lane b (b < 15) owns bin b.
    float r_cnt = 0.0f, r_conf = 0.0f, r_acc = 0.0f;

    if (vec_ok) {
        const float4* __restrict__ lg = reinterpret_cast<const float4*>(logits);

        // ---- depth-2 software pipeline: row i+1's loads issue before
        //      row i's reduction chain consumes row i's data. ----
        int row = warp;
        float4 v = make_float4(0.f, 0.f, 0.f, 0.f);
        int lab = 0;
        if (row < n) {
            if (lane < 25) v = lg[(size_t)row * 25 + lane];
            lab = is64 ? (int)lab64[row] : lab32[row];
        }

        while (row < n) {
            const int next = row + nwarps;
            float4 v2 = make_float4(0.f, 0.f, 0.f, 0.f);
            int lab2 = 0;
            if (next < n) {                       // prefetch next row
                if (lane < 25) v2 = lg[(size_t)next * 25 + lane];
                lab2 = is64 ? (int)lab64[next] : lab32[next];
            }

            // ---- reduce current row ----
            float m  = -CUDART_INF_F;
            int   mi = 0x7fffffff;
            if (lane < 25) {
                int base = lane * 4;
                m = v.x; mi = base;                      // strict > keeps
                if (v.y > m) { m = v.y; mi = base + 1; } // first index
                if (v.z > m) { m = v.z; mi = base + 2; }
                if (v.w > m) { m = v.w; mi = base + 3; }
            }

            unsigned mu   = fmap(m);
            unsigned maxu = __reduce_max_sync(FULL, mu);
            unsigned wm   = __ballot_sync(FULL, mu == maxu);
            int src = __ffs(wm) - 1;      // lowest lane == first index group
            float mm  = __shfl_sync(FULL, m,  src);
            int   ami = __shfl_sync(FULL, mi, src);

            float conf = 1.0f / (1.0f + __expf(-mm));   // sigmoid monotone
            int bin = (int)ceilf(conf * 15.0f) - 1;     // searchsorted-left - 1
            bin = bin < 0 ? 0 : (bin > N_BINS - 1 ? N_BINS - 1 : bin);

            if (lane == bin) {
                r_cnt  += 1.0f;
                r_conf += conf;
                r_acc  += (ami == lab) ? 1.0f : 0.0f;
            }

            row = next; v = v2; lab = lab2;
        }
    } else {
        // scalar fallback (unaligned logits base)
        for (int row = warp; row < n; row += nwarps) {
            float m = -CUDART_INF_F; int mi = 0x7fffffff;
            #pragma unroll
            for (int j = 0; j < 4; j++) {
                int c = lane + j * 32;
                if (c < C_DIM) {
                    float x = logits[(size_t)row * C_DIM + c];
                    if (x > m) { m = x; mi = c; }
                }
            }
            int lab = is64 ? (int)lab64[row] : lab32[row];
            unsigned mu   = fmap(m);
            unsigned maxu = __reduce_max_sync(FULL, mu);
            unsigned wm   = __ballot_sync(FULL, mu == maxu);
            int src = __ffs(wm) - 1;
            float mm  = __shfl_sync(FULL, m,  src);
            int   ami = __shfl_sync(FULL, mi, src);
            float conf = 1.0f / (1.0f + __expf(-mm));
            int bin = (int)ceilf(conf * 15.0f) - 1;
            bin = bin < 0 ? 0 : (bin > N_BINS - 1 ? N_BINS - 1 : bin);
            if (lane == bin) {
                r_cnt += 1.0f; r_conf += conf;
                r_acc += (ami == lab) ? 1.0f : 0.0f;
            }
        }
    }

    // Flush: 3 global atomics per lane (<15) per warp for the whole kernel.
    if (lane < N_BINS && r_cnt != 0.0f) {
        atomicAdd(&g_cnt[lane],  r_cnt);
        atomicAdd(&g_conf[lane], (double)r_conf);
        atomicAdd(&g_accs[lane], r_acc);
    }
}

__global__ void ece_final_kernel(float* __restrict__ out, float inv_n) {
    if (threadIdx.x == 0 && blockIdx.x == 0) {
        float ece = 0.0f;
        #pragma unroll
        for (int b = 0; b < N_BINS; b++) {
            float cnt = g_cnt[b];
            if (cnt > 0.0f) {
                float avg_conf = (float)g_conf[b] / cnt;
                float avg_acc  = g_accs[b] / cnt;
                ece += (avg_conf - avg_acc) * (cnt * inv_n);
            }
        }
        out[0] = ece;
    }
}

extern "C" void kernel_launch(void* const* d_in, const int* in_sizes, int n_in,
                              void* d_out, int out_size) {
    // Resolve input order by element count (logits = C_DIM x labels count).
    long long s0 = in_sizes[0], s1 = in_sizes[1];
    int logits_idx = (s0 > s1) ? 0 : 1;
    int labels_idx = 1 - logits_idx;

    const float* logits     = (const float*)d_in[logits_idx];
    const void*  labels_raw = d_in[labels_idx];
    int n = (int)((s0 < s1) ? s0 : s1);
    float* out = (float*)d_out;

    int vec_ok = ((uintptr_t)logits & 15) == 0 ? 1 : 0;

    ece_zero_kernel<<<1, 64>>>((const int*)labels_raw, n);
    ece_accum_kernel<<<BLOCKS, THREADS>>>(logits, labels_raw, n, vec_ok);
    ece_final_kernel<<<1, 32>>>(out, 1.0f / (float)n);
}